// round 2
// baseline (speedup 1.0000x reference)
#include <cuda_runtime.h>
#include <math_constants.h>

#define D_DIM 64
#define K_CODES 2048
#define NVEC 131072                 // 16*1024*8 vectors
#define BM 64
#define BN 128
#define CODES_ELEMS (NVEC * D_DIM)  // 8388608
#define NBLOCKS (NVEC / BM)         // 2048

#define ZSD_STRIDE 66               // float2 row stride (pad for bank spread, keeps 16B align)
#define SMEM_ZSD_BYTES (D_DIM * ZSD_STRIDE * 8)          // 33792
#define SMEM_CS_BYTES (D_DIM * BN * 4)                   // 32768
#define SMEM_TOTAL (SMEM_ZSD_BYTES + SMEM_CS_BYTES + BN * 4 + BM * 4 + 256 * 4)

__device__ float g_cnorm[K_CODES];
__device__ float g_partials[NBLOCKS];

#define FMA2(d, a, b) \
    asm("fma.rn.f32x2 %0, %1, %2, %0;" : "+l"(d) : "l"(a), "l"(b))
#define UNPK2(lo, hi, p) \
    asm("mov.b64 {%0,%1}, %2;" : "=f"(lo), "=f"(hi) : "l"(p))

// ---------------------------------------------------------------------------
// Kernel 1: codebook squared norms
// ---------------------------------------------------------------------------
__global__ void cnorm_kernel(const float* __restrict__ cb) {
    int k = blockIdx.x * blockDim.x + threadIdx.x;
    if (k < K_CODES) {
        const float4* row = (const float4*)(cb + (size_t)k * D_DIM);
        float s = 0.f;
#pragma unroll
        for (int i = 0; i < D_DIM / 4; i++) {
            float4 v = row[i];
            s += v.x * v.x + v.y * v.y + v.z * v.z + v.w * v.w;
        }
        g_cnorm[k] = s;
    }
}

// ---------------------------------------------------------------------------
// Kernel 2: distance GEMM (packed f32x2) + argmin + gather + commit partial
// ---------------------------------------------------------------------------
__global__ __launch_bounds__(256, 2) void vq_kernel(const float* __restrict__ z,
                                                    const float* __restrict__ cb,
                                                    float* __restrict__ out) {
    extern __shared__ char dynsmem[];
    float2* zsd = (float2*)dynsmem;                       // [64][66] dup'd z, K-major
    float* cs = (float*)(dynsmem + SMEM_ZSD_BYTES);       // [64][128] codes, K-major, swizzled
    float* cn = cs + D_DIM * BN;                          // [128]
    int* sidx = (int*)(cn + BN);                          // [64]
    float* red = (float*)(sidx + BM);                     // [256]

    const int tid = threadIdx.x;
    const int m0 = blockIdx.x * BM;
    const int trow = tid >> 4;       // 0..15 -> rows trow*4..+3
    const int tcol = tid & 15;       // 0..15 -> cols tcol*8..+7
    const int trow4 = trow * 4;

    // --- Load z tile, transposed + lane-duplicated into zsd (one time) ---
#pragma unroll
    for (int it = 0; it < 4; it++) {
        int e = tid + it * 256;          // 0..1023
        int row = e >> 4;                // 0..63
        int dq = e & 15;                 // float4 index along d
        float4 v = *(const float4*)(z + (size_t)(m0 + row) * D_DIM + dq * 4);
        zsd[(dq * 4 + 0) * ZSD_STRIDE + row] = make_float2(v.x, v.x);
        zsd[(dq * 4 + 1) * ZSD_STRIDE + row] = make_float2(v.y, v.y);
        zsd[(dq * 4 + 2) * ZSD_STRIDE + row] = make_float2(v.z, v.z);
        zsd[(dq * 4 + 3) * ZSD_STRIDE + row] = make_float2(v.w, v.w);
    }

    float bestv[4];
    int besti[4];
#pragma unroll
    for (int i = 0; i < 4; i++) { bestv[i] = CUDART_INF_F; besti[i] = 0; }

    for (int k0 = 0; k0 < K_CODES; k0 += BN) {
        __syncthreads();  // protect cs/cn from previous iteration's readers
        // Codebook tile -> K-major smem with XOR-swizzled col (kills STS conflicts)
#pragma unroll
        for (int it = 0; it < 8; it++) {
            int e = tid + it * 256;      // 0..2047
            int col = e >> 4;            // 0..127
            int dq = e & 15;
            float4 v = *(const float4*)(cb + (size_t)(k0 + col) * D_DIM + dq * 4);
            int csw = col ^ ((dq & 7) << 2);
            int kb = dq * 4;
            cs[(kb + 0) * BN + csw] = v.x;
            cs[(kb + 1) * BN + csw] = v.y;
            cs[(kb + 2) * BN + csw] = v.z;
            cs[(kb + 3) * BN + csw] = v.w;
        }
        if (tid < BN) cn[tid] = g_cnorm[k0 + tid];
        __syncthreads();

        unsigned long long acc[4][4];    // [row][colpair] packed f32x2
#pragma unroll
        for (int i = 0; i < 4; i++)
#pragma unroll
            for (int j = 0; j < 4; j++) acc[i][j] = 0ULL;

#pragma unroll 8
        for (int k = 0; k < D_DIM; k++) {
            // a: duplicated row pairs  (a_i, a_i)
            ulonglong2 a01 = *(const ulonglong2*)(zsd + k * ZSD_STRIDE + trow4);
            ulonglong2 a23 = *(const ulonglong2*)(zsd + k * ZSD_STRIDE + trow4 + 2);
            // b: natural col pairs from swizzled K-major tile
            int k7 = (k >> 2) & 7;
            const ulonglong2* bq = (const ulonglong2*)(cs + k * BN);
            int pq0 = (tcol * 2) ^ k7;
            ulonglong2 blo = bq[pq0];
            ulonglong2 bhi = bq[pq0 ^ 1];
            unsigned long long ad[4] = {a01.x, a01.y, a23.x, a23.y};
            unsigned long long bp[4] = {blo.x, blo.y, bhi.x, bhi.y};
#pragma unroll
            for (int i = 0; i < 4; i++)
#pragma unroll
                for (int j = 0; j < 4; j++) FMA2(acc[i][j], ad[i], bp[j]);
        }

        // dist = ||c||^2 - 2*dot  (row-constant ||z||^2 dropped for argmin)
#pragma unroll
        for (int jp = 0; jp < 4; jp++) {
            int c0 = tcol * 8 + 2 * jp;
            float cA = cn[c0], cB = cn[c0 + 1];
#pragma unroll
            for (int i = 0; i < 4; i++) {
                float dlo, dhi;
                UNPK2(dlo, dhi, acc[i][jp]);
                float vA = fmaf(-2.f, dlo, cA);
                if (vA < bestv[i]) { bestv[i] = vA; besti[i] = k0 + c0; }
                float vB = fmaf(-2.f, dhi, cB);
                if (vB < bestv[i]) { bestv[i] = vB; besti[i] = k0 + c0 + 1; }
            }
        }
    }

    // Reduce across the 16 threads sharing each row group (width-16 segments)
#pragma unroll
    for (int off = 8; off >= 1; off >>= 1) {
#pragma unroll
        for (int i = 0; i < 4; i++) {
            float ov = __shfl_down_sync(0xffffffffu, bestv[i], off, 16);
            int oi = __shfl_down_sync(0xffffffffu, besti[i], off, 16);
            if (ov < bestv[i] || (ov == bestv[i] && oi < besti[i])) {
                bestv[i] = ov;
                besti[i] = oi;
            }
        }
    }
    if (tcol == 0) {
#pragma unroll
        for (int i = 0; i < 4; i++) sidx[trow4 + i] = besti[i];
    }
    __syncthreads();

    // Epilogue: gather codebook rows (codes), write indices, commit partial
    float lsum = 0.f;
#pragma unroll
    for (int it = 0; it < 16; it++) {
        int e = tid + it * 256;   // 0..4095
        int row = e >> 6;
        int d = e & 63;
        int ci = sidx[row];
        float cv = __ldg(cb + (size_t)ci * D_DIM + d);
        float zv = zsd[d * ZSD_STRIDE + row].x;
        float diff = cv - zv;
        lsum += diff * diff;
        out[(size_t)(m0 + row) * D_DIM + d] = cv;
    }
    if (tid < BM) out[CODES_ELEMS + m0 + tid] = (float)sidx[tid];

    red[tid] = lsum;
    __syncthreads();
#pragma unroll
    for (int s = 128; s > 0; s >>= 1) {
        if (tid < s) red[tid] += red[tid + s];
        __syncthreads();
    }
    if (tid == 0) g_partials[blockIdx.x] = red[0];
}

// ---------------------------------------------------------------------------
// Kernel 3: deterministic commit-loss reduction (fixed order, double accum)
// ---------------------------------------------------------------------------
__global__ void final_kernel(float* __restrict__ out) {
    __shared__ double dred[256];
    int tid = threadIdx.x;
    double s = 0.0;
    for (int i = tid; i < NBLOCKS; i += 256) s += (double)g_partials[i];
    dred[tid] = s;
    __syncthreads();
#pragma unroll
    for (int st = 128; st > 0; st >>= 1) {
        if (tid < st) dred[tid] += dred[tid + st];
        __syncthreads();
    }
    if (tid == 0)
        out[CODES_ELEMS + NVEC] = (float)(dred[0] / (double)CODES_ELEMS);
}

// ---------------------------------------------------------------------------
extern "C" void kernel_launch(void* const* d_in, const int* in_sizes, int n_in,
                              void* d_out, int out_size) {
    const float* z = (const float*)d_in[0];
    const float* cb = (const float*)d_in[1];
    if (n_in >= 2 && in_sizes[0] < in_sizes[1]) {
        const float* t = z; z = cb; cb = t;
    }
    float* out = (float*)d_out;

    cudaFuncSetAttribute(vq_kernel, cudaFuncAttributeMaxDynamicSharedMemorySize,
                         SMEM_TOTAL);

    cnorm_kernel<<<(K_CODES + 255) / 256, 256>>>(cb);
    vq_kernel<<<NBLOCKS, 256, SMEM_TOTAL>>>(z, cb, out);
    final_kernel<<<1, 256>>>(out);
}

// round 5
// speedup vs baseline: 1.7189x; 1.7189x over previous
#include <cuda_runtime.h>
#include <cuda_bf16.h>
#include <math_constants.h>
#include <cstdint>

#define D_DIM 64
#define K_CODES 2048
#define NVEC 131072
#define CODES_ELEMS (NVEC * D_DIM)
#define MTILE 256                    // rows per CTA
#define BN 128                       // codes per chunk
#define NCHUNKS (K_CODES / BN)       // 16
#define KV 192                       // virtual K: zh*ch + zh*cl + zl*ch
#define KSTEPS (KV / 16)             // 12
#define NCTAS (NVEC / MTILE)         // 512
#define OUTBLOCKS 2048
#define MARGIN 1e-2f

#define RSTRIDE 400                  // bytes per K-row (192*2=384, pad to 400 -> ldsm conflict-free)
#define SM_A 0                       // 256*400 = 102400
#define SM_B0 102400                 // 128*400 = 51200
#define SM_B1 153600
#define SMEM_K2 204800

__device__ __align__(16) __nv_bfloat16 g_Bg[K_CODES * KV];  // packed codebook [ch|cl|ch]
__device__ float g_cnorm[K_CODES];
__device__ int g_besti[NVEC];
__device__ int g_flags[NVEC];
__device__ int g_nflag;
__device__ float g_partials[OUTBLOCKS];

// ---------------- PTX helpers (all base-sm_103 legal: no 'a' features) -----
__device__ __forceinline__ uint32_t smem_u32(const void* p) {
    uint32_t a;
    asm("{ .reg .u64 t; cvta.to.shared.u64 t, %1; cvt.u32.u64 %0, t; }"
        : "=r"(a) : "l"(p));
    return a;
}
#define CP16(dst, src) \
    asm volatile("cp.async.cg.shared.global [%0], [%1], 16;" :: "r"(dst), "l"(src))
#define CP_COMMIT() asm volatile("cp.async.commit_group;" ::: "memory")
#define CP_WAIT0() asm volatile("cp.async.wait_group 0;" ::: "memory")

#define LDSM4(r0, r1, r2, r3, addr)                                         \
    asm volatile("ldmatrix.sync.aligned.m8n8.x4.shared.b16 {%0,%1,%2,%3},[%4];" \
                 : "=r"(r0), "=r"(r1), "=r"(r2), "=r"(r3) : "r"(addr))

#define MMA16816(c, a, b0, b1)                                              \
    asm volatile(                                                           \
        "mma.sync.aligned.m16n8k16.row.col.f32.bf16.bf16.f32 "              \
        "{%0,%1,%2,%3},{%4,%5,%6,%7},{%8,%9},{%0,%1,%2,%3};"                \
        : "+f"((c)[0]), "+f"((c)[1]), "+f"((c)[2]), "+f"((c)[3])            \
        : "r"((a)[0]), "r"((a)[1]), "r"((a)[2]), "r"((a)[3]),               \
          "r"(b0), "r"(b1))

// ---------------------------------------------------------------------------
// K0: reset flag counter
// ---------------------------------------------------------------------------
__global__ void reset_kernel() { g_nflag = 0; }

// ---------------------------------------------------------------------------
// K1: cnorm + packed split codebook [ch | cl | ch]
// ---------------------------------------------------------------------------
__global__ void prep_kernel(const float* __restrict__ cb) {
    int n = blockIdx.x * blockDim.x + threadIdx.x;
    if (n >= K_CODES) return;
    const float4* row = (const float4*)(cb + (size_t)n * D_DIM);
    float s = 0.f;
    __nv_bfloat16* bg = g_Bg + (size_t)n * KV;
#pragma unroll
    for (int i = 0; i < D_DIM / 4; i++) {
        float4 v = row[i];
        s += v.x * v.x + v.y * v.y + v.z * v.z + v.w * v.w;
        float vv[4] = {v.x, v.y, v.z, v.w};
#pragma unroll
        for (int j = 0; j < 4; j++) {
            int d = i * 4 + j;
            __nv_bfloat16 h = __float2bfloat16(vv[j]);
            __nv_bfloat16 l = __float2bfloat16(vv[j] - __bfloat162float(h));
            bg[d] = h;         // ch  (pairs A's zh)
            bg[64 + d] = l;    // cl  (pairs A's zh)
            bg[128 + d] = h;   // ch  (pairs A's zl)
        }
    }
    g_cnorm[n] = s;
}

// ---------------------------------------------------------------------------
// K2: HMMA (mma.sync bf16) distance GEMM + argmin(best,second) + flags
// ---------------------------------------------------------------------------
__global__ __launch_bounds__(256, 1) void vq_mma_kernel(const float* __restrict__ z) {
    extern __shared__ char smem[];
    const uint32_t sb = smem_u32(smem);
    const int tid = threadIdx.x;
    const int wid = tid >> 5;
    const int lane = tid & 31;
    const int mband = wid >> 1;      // 0..3 -> rows mband*64 .. +63
    const int nband = wid & 1;       // 0..1 -> cols nband*64 .. +63 of each chunk
    const int wm = mband * 64;
    const int wn = nband * 64;
    const int m0 = blockIdx.x * MTILE;

    // ---- issue chunk-0 B load first (overlaps A fill) ----
    {
        const char* src0 = (const char*)g_Bg;
#pragma unroll
        for (int it = 0; it < 12; it++) {
            int u = tid + it * 256;          // 0..3071
            int row = u / 24;
            int c16 = u - row * 24;
            CP16(sb + SM_B0 + row * RSTRIDE + c16 * 16,
                 src0 + (size_t)row * (KV * 2) + c16 * 16);
        }
        CP_COMMIT();
    }

    // ---- A fill: z rows -> bf16 split [zh | zh | zl], padded K-major ----
#pragma unroll
    for (int it = 0; it < 16; it++) {
        int u = tid + it * 256;              // 0..4095 float4s
        int row = u >> 4;
        int q = u & 15;
        float4 v = *(const float4*)(z + (size_t)(m0 + row) * D_DIM + q * 4);
        float vv[4] = {v.x, v.y, v.z, v.w};
        uint32_t hp[2], lp[2];
#pragma unroll
        for (int pr = 0; pr < 2; pr++) {
            __nv_bfloat16 h0 = __float2bfloat16(vv[2 * pr]);
            __nv_bfloat16 h1 = __float2bfloat16(vv[2 * pr + 1]);
            __nv_bfloat16 l0 = __float2bfloat16(vv[2 * pr] - __bfloat162float(h0));
            __nv_bfloat16 l1 = __float2bfloat16(vv[2 * pr + 1] - __bfloat162float(h1));
            __nv_bfloat162 hh = {h0, h1}, ll = {l0, l1};
            hp[pr] = *(uint32_t*)&hh;
            lp[pr] = *(uint32_t*)&ll;
        }
        char* base = smem + SM_A + row * RSTRIDE;
        int c = q * 4;
#pragma unroll
        for (int pr = 0; pr < 2; pr++) {
            int cc = c + 2 * pr;
            *(uint32_t*)(base + cc * 2) = hp[pr];
            *(uint32_t*)(base + (cc + 64) * 2) = hp[pr];
            *(uint32_t*)(base + (cc + 128) * 2) = lp[pr];
        }
    }

    // ---- ldmatrix lane address offsets (bytes) ----
    uint32_t aoff[4];
#pragma unroll
    for (int i = 0; i < 4; i++)
        aoff[i] = sb + SM_A + (wm + i * 16 + (lane & 15)) * RSTRIDE + ((lane >> 4) * 16);
    uint32_t boff[4];
#pragma unroll
    for (int jj = 0; jj < 4; jj++)
        boff[jj] = (uint32_t)((wn + jj * 16 + ((lane >> 4) * 8) + (lane & 7)) * RSTRIDE +
                              (((lane >> 3) & 1) * 16));

    float bv[8], sv[8];
    int bi[8];
#pragma unroll
    for (int s = 0; s < 8; s++) { bv[s] = CUDART_INF_F; sv[s] = CUDART_INF_F; bi[s] = 0; }

    CP_WAIT0();
    __syncthreads();

    const char* BgB = (const char*)g_Bg;
    for (int ch = 0; ch < NCHUNKS; ch++) {
        // prefetch next chunk into other buffer (that buffer's readers synced out)
        if (ch < NCHUNKS - 1) {
            uint32_t dstb = sb + (((ch + 1) & 1) ? SM_B1 : SM_B0);
            const char* src = BgB + (size_t)(ch + 1) * BN * (KV * 2);
#pragma unroll
            for (int it = 0; it < 12; it++) {
                int u = tid + it * 256;
                int row = u / 24;
                int c16 = u - row * 24;
                CP16(dstb + row * RSTRIDE + c16 * 16,
                     src + (size_t)row * (KV * 2) + c16 * 16);
            }
            CP_COMMIT();
        }

        const uint32_t bbuf = sb + ((ch & 1) ? SM_B1 : SM_B0);
        float acc[4][8][4];
#pragma unroll
        for (int m = 0; m < 4; m++)
#pragma unroll
            for (int j = 0; j < 8; j++)
#pragma unroll
                for (int e = 0; e < 4; e++) acc[m][j][e] = 0.f;

#pragma unroll 4
        for (int k = 0; k < KSTEPS; k++) {
            uint32_t af[4][4], bf[4][4];
#pragma unroll
            for (int m = 0; m < 4; m++)
                LDSM4(af[m][0], af[m][1], af[m][2], af[m][3], aoff[m] + k * 32);
#pragma unroll
            for (int jj = 0; jj < 4; jj++)
                LDSM4(bf[jj][0], bf[jj][1], bf[jj][2], bf[jj][3],
                      bbuf + boff[jj] + k * 32);
#pragma unroll
            for (int m = 0; m < 4; m++)
#pragma unroll
                for (int j = 0; j < 8; j++)
                    MMA16816(acc[m][j], af[m], bf[j >> 1][(j & 1) * 2],
                             bf[j >> 1][(j & 1) * 2 + 1]);
        }

        // epilogue: dist = cnorm - 2*dot; track best/second per row-slot
        const int cb = ch * BN + wn;
#pragma unroll
        for (int j = 0; j < 8; j++) {
            int c0 = cb + j * 8 + 2 * (lane & 3);
            float cn0 = __ldg(g_cnorm + c0);
            float cn1 = __ldg(g_cnorm + c0 + 1);
#pragma unroll
            for (int m = 0; m < 4; m++) {
                float v00 = fmaf(-2.f, acc[m][j][0], cn0);
                float v01 = fmaf(-2.f, acc[m][j][1], cn1);
                float v10 = fmaf(-2.f, acc[m][j][2], cn0);
                float v11 = fmaf(-2.f, acc[m][j][3], cn1);
                int s0 = m * 2, s1 = m * 2 + 1;
                if (v00 < bv[s0]) { sv[s0] = bv[s0]; bv[s0] = v00; bi[s0] = c0; }
                else if (v00 < sv[s0]) sv[s0] = v00;
                if (v01 < bv[s0]) { sv[s0] = bv[s0]; bv[s0] = v01; bi[s0] = c0 + 1; }
                else if (v01 < sv[s0]) sv[s0] = v01;
                if (v10 < bv[s1]) { sv[s1] = bv[s1]; bv[s1] = v10; bi[s1] = c0; }
                else if (v10 < sv[s1]) sv[s1] = v10;
                if (v11 < bv[s1]) { sv[s1] = bv[s1]; bv[s1] = v11; bi[s1] = c0 + 1; }
                else if (v11 < sv[s1]) sv[s1] = v11;
            }
        }

        if (ch < NCHUNKS - 1) CP_WAIT0();
        __syncthreads();
    }

    // ---- quad reduce (lanes sharing a row: lane&3 = 0..3) ----
#pragma unroll
    for (int off = 1; off <= 2; off <<= 1) {
#pragma unroll
        for (int s = 0; s < 8; s++) {
            float ov = __shfl_xor_sync(0xffffffffu, bv[s], off);
            float os = __shfl_xor_sync(0xffffffffu, sv[s], off);
            int oi = __shfl_xor_sync(0xffffffffu, bi[s], off);
            if (ov < bv[s] || (ov == bv[s] && oi < bi[s])) {
                sv[s] = fminf(os, bv[s]);
                bv[s] = ov;
                bi[s] = oi;
            } else {
                sv[s] = fminf(sv[s], ov);
            }
        }
    }

    // ---- cross-warp (N-band) merge via smem scratch (reuse B0 region) ----
    float* mvS = (float*)(smem + SM_B0);
    float* msS = mvS + 512;
    int* miS = (int*)(msS + 512);
    if ((lane & 3) == 0) {
#pragma unroll
        for (int s = 0; s < 8; s++) {
            int gr = wm + (s >> 1) * 16 + (s & 1) * 8 + (lane >> 2);  // 0..255
            int idx = nband * 256 + gr;
            mvS[idx] = bv[s];
            msS[idx] = sv[s];
            miS[idx] = bi[s];
        }
    }
    __syncthreads();
    {
        int gr = tid;
        float b0v = mvS[gr], s0v = msS[gr];
        int b0i = miS[gr];
        float b1v = mvS[256 + gr], s1v = msS[256 + gr];
        int b1i = miS[256 + gr];
        float b, s2;
        int biF;
        if (b1v < b0v || (b1v == b0v && b1i < b0i)) {
            b = b1v; biF = b1i; s2 = fminf(s1v, b0v);
        } else {
            b = b0v; biF = b0i; s2 = fminf(s0v, b1v);
        }
        int row = m0 + gr;
        g_besti[row] = biF;
        if (s2 - b <= MARGIN) {
            int slot = atomicAdd(&g_nflag, 1);
            g_flags[slot] = row;
        }
    }
}

// ---------------------------------------------------------------------------
// K3: exact fp32 re-scan for ambiguous rows
// ---------------------------------------------------------------------------
__global__ __launch_bounds__(256) void fallback_kernel(const float* __restrict__ z,
                                                       const float* __restrict__ cb) {
    __shared__ float zrow[D_DIM];
    __shared__ float rv[256];
    __shared__ int ri[256];
    const int tid = threadIdx.x;
    const int nf = g_nflag;
    for (int f = blockIdx.x; f < nf; f += gridDim.x) {
        int row = g_flags[f];
        if (tid < D_DIM) zrow[tid] = z[(size_t)row * D_DIM + tid];
        __syncthreads();
        float bvv = CUDART_INF_F;
        int bii = 0;
        for (int k = tid; k < K_CODES; k += 256) {
            const float* c = cb + (size_t)k * D_DIM;
            float dot = 0.f;
#pragma unroll
            for (int j = 0; j < D_DIM; j++) dot = fmaf(zrow[j], c[j], dot);
            float d = fmaf(-2.f, dot, g_cnorm[k]);
            if (d < bvv) { bvv = d; bii = k; }
        }
        rv[tid] = bvv;
        ri[tid] = bii;
        __syncthreads();
        for (int s = 128; s > 0; s >>= 1) {
            if (tid < s) {
                float ov = rv[tid + s];
                int oi = ri[tid + s];
                if (ov < rv[tid] || (ov == rv[tid] && oi < ri[tid])) {
                    rv[tid] = ov;
                    ri[tid] = oi;
                }
            }
            __syncthreads();
        }
        if (tid == 0) g_besti[row] = ri[0];
        __syncthreads();
    }
}

// ---------------------------------------------------------------------------
// K4: outputs — gather codes, indices, commit partials
// ---------------------------------------------------------------------------
__global__ __launch_bounds__(256) void output_kernel(const float* __restrict__ z,
                                                     const float* __restrict__ cb,
                                                     float* __restrict__ out) {
    __shared__ float red[256];
    const int tid = threadIdx.x;
    const int m0 = blockIdx.x * 64;
    float lsum = 0.f;
#pragma unroll
    for (int it = 0; it < 16; it++) {
        int e = tid + it * 256;
        int row = e >> 6;
        int d = e & 63;
        int ci = g_besti[m0 + row];
        float cv = __ldg(cb + (size_t)ci * D_DIM + d);
        float zv = z[(size_t)(m0 + row) * D_DIM + d];
        float diff = cv - zv;
        lsum += diff * diff;
        out[(size_t)(m0 + row) * D_DIM + d] = cv;
    }
    if (tid < 64) out[CODES_ELEMS + m0 + tid] = (float)g_besti[m0 + tid];
    red[tid] = lsum;
    __syncthreads();
#pragma unroll
    for (int s = 128; s > 0; s >>= 1) {
        if (tid < s) red[tid] += red[tid + s];
        __syncthreads();
    }
    if (tid == 0) g_partials[blockIdx.x] = red[0];
}

// ---------------------------------------------------------------------------
// K5: deterministic commit-loss reduction
// ---------------------------------------------------------------------------
__global__ void final_kernel(float* __restrict__ out) {
    __shared__ double dred[256];
    int tid = threadIdx.x;
    double s = 0.0;
    for (int i = tid; i < OUTBLOCKS; i += 256) s += (double)g_partials[i];
    dred[tid] = s;
    __syncthreads();
#pragma unroll
    for (int st = 128; st > 0; st >>= 1) {
        if (tid < st) dred[tid] += dred[tid + st];
        __syncthreads();
    }
    if (tid == 0)
        out[CODES_ELEMS + NVEC] = (float)(dred[0] / (double)CODES_ELEMS);
}

// ---------------------------------------------------------------------------
extern "C" void kernel_launch(void* const* d_in, const int* in_sizes, int n_in,
                              void* d_out, int out_size) {
    const float* z = (const float*)d_in[0];
    const float* cb = (const float*)d_in[1];
    if (n_in >= 2 && in_sizes[0] < in_sizes[1]) {
        const float* t = z; z = cb; cb = t;
    }
    float* out = (float*)d_out;

    cudaFuncSetAttribute(vq_mma_kernel,
                         cudaFuncAttributeMaxDynamicSharedMemorySize, SMEM_K2);

    reset_kernel<<<1, 1>>>();
    prep_kernel<<<(K_CODES + 255) / 256, 256>>>(cb);
    vq_mma_kernel<<<NCTAS, 256, SMEM_K2>>>(z);
    fallback_kernel<<<256, 256>>>(z, cb);
    output_kernel<<<OUTBLOCKS, 256>>>(z, cb, out);
    final_kernel<<<1, 256>>>(out);
}

// round 6
// speedup vs baseline: 2.2370x; 1.3014x over previous
#include <cuda_runtime.h>
#include <cuda_bf16.h>
#include <math_constants.h>
#include <cstdint>

#define D_DIM 64
#define K_CODES 2048
#define NVEC 131072
#define CODES_ELEMS (NVEC * D_DIM)
#define MTILE 256                    // rows per CTA
#define BN 128                       // codes per chunk
#define NCHUNKS (K_CODES / BN)       // 16
#define KV 192                       // virtual K: zh*ch + zh*cl + zl*ch
#define KSTEPS (KV / 16)             // 12
#define NCTAS (NVEC / MTILE)         // 512
#define OUTBLOCKS 2048
#define ACCSLACK 3e-3f

#define RSTRIDE 400                  // bytes per K-row (192*2=384, pad to 400 -> ldsm conflict-free)
#define SM_A 0                       // 256*400 = 102400
#define SM_B0 102400                 // 128*400 = 51200
#define SM_B1 153600
#define SM_ZLN 204800                // 256 floats: per-row ||zl||^2
#define SMEM_K2 205824

__device__ __align__(16) __nv_bfloat16 g_Bg[K_CODES * KV];  // packed codebook [ch|cl|ch]
__device__ float g_cnorm[K_CODES];
__device__ unsigned int g_maxcl2;    // max over codes of ||cl||^2 (float bits)
__device__ int g_besti[NVEC];
__device__ int g_flags[NVEC];
__device__ int g_nflag;
__device__ float g_partials[OUTBLOCKS];

// ---------------- PTX helpers (all base-sm_103 legal: no 'a' features) -----
__device__ __forceinline__ uint32_t smem_u32(const void* p) {
    uint32_t a;
    asm("{ .reg .u64 t; cvta.to.shared.u64 t, %1; cvt.u32.u64 %0, t; }"
        : "=r"(a) : "l"(p));
    return a;
}
#define CP16(dst, src) \
    asm volatile("cp.async.cg.shared.global [%0], [%1], 16;" :: "r"(dst), "l"(src))
#define CP_COMMIT() asm volatile("cp.async.commit_group;" ::: "memory")
#define CP_WAIT0() asm volatile("cp.async.wait_group 0;" ::: "memory")

#define LDSM4(r0, r1, r2, r3, addr)                                         \
    asm volatile("ldmatrix.sync.aligned.m8n8.x4.shared.b16 {%0,%1,%2,%3},[%4];" \
                 : "=r"(r0), "=r"(r1), "=r"(r2), "=r"(r3) : "r"(addr))

#define MMA16816(c, a, b0, b1)                                              \
    asm volatile(                                                           \
        "mma.sync.aligned.m16n8k16.row.col.f32.bf16.bf16.f32 "              \
        "{%0,%1,%2,%3},{%4,%5,%6,%7},{%8,%9},{%0,%1,%2,%3};"                \
        : "+f"((c)[0]), "+f"((c)[1]), "+f"((c)[2]), "+f"((c)[3])            \
        : "r"((a)[0]), "r"((a)[1]), "r"((a)[2]), "r"((a)[3]),               \
          "r"(b0), "r"(b1))

// ---------------------------------------------------------------------------
// K0: reset counters
// ---------------------------------------------------------------------------
__global__ void reset_kernel() { g_nflag = 0; g_maxcl2 = 0u; }

// ---------------------------------------------------------------------------
// K1: cnorm + packed split codebook [ch | cl | ch] + max ||cl||^2
// ---------------------------------------------------------------------------
__global__ void prep_kernel(const float* __restrict__ cb) {
    int n = blockIdx.x * blockDim.x + threadIdx.x;
    if (n >= K_CODES) return;
    const float4* row = (const float4*)(cb + (size_t)n * D_DIM);
    float s = 0.f, cl2 = 0.f;
    __nv_bfloat16* bg = g_Bg + (size_t)n * KV;
#pragma unroll
    for (int i = 0; i < D_DIM / 4; i++) {
        float4 v = row[i];
        s += v.x * v.x + v.y * v.y + v.z * v.z + v.w * v.w;
        float vv[4] = {v.x, v.y, v.z, v.w};
#pragma unroll
        for (int j = 0; j < 4; j++) {
            int d = i * 4 + j;
            __nv_bfloat16 h = __float2bfloat16(vv[j]);
            float lf = vv[j] - __bfloat162float(h);
            __nv_bfloat16 l = __float2bfloat16(lf);
            cl2 += lf * lf;
            bg[d] = h;         // ch  (pairs A's zh)
            bg[64 + d] = l;    // cl  (pairs A's zh)
            bg[128 + d] = h;   // ch  (pairs A's zl)
        }
    }
    g_cnorm[n] = s;
    atomicMax(&g_maxcl2, __float_as_uint(cl2));   // positive floats: bit-monotonic
}

// ---------------------------------------------------------------------------
// K2: HMMA (mma.sync bf16) distance GEMM + argmin(best,second) + flags
// ---------------------------------------------------------------------------
__global__ __launch_bounds__(256, 1) void vq_mma_kernel(const float* __restrict__ z) {
    extern __shared__ char smem[];
    const uint32_t sb = smem_u32(smem);
    const int tid = threadIdx.x;
    const int wid = tid >> 5;
    const int lane = tid & 31;
    const int mband = wid >> 1;      // 0..3 -> rows mband*64 .. +63
    const int nband = wid & 1;       // 0..1 -> cols nband*64 .. +63 of each chunk
    const int wm = mband * 64;
    const int wn = nband * 64;
    const int m0 = blockIdx.x * MTILE;
    float* zln2 = (float*)(smem + SM_ZLN);

    // ---- issue chunk-0 B load first (overlaps A fill) ----
    {
        const char* src0 = (const char*)g_Bg;
#pragma unroll
        for (int it = 0; it < 12; it++) {
            int u = tid + it * 256;          // 0..3071
            int row = u / 24;
            int c16 = u - row * 24;
            CP16(sb + SM_B0 + row * RSTRIDE + c16 * 16,
                 src0 + (size_t)row * (KV * 2) + c16 * 16);
        }
        CP_COMMIT();
    }

    // ---- A fill: z rows -> bf16 split [zh | zh | zl], + per-row ||zl||^2 ----
#pragma unroll
    for (int it = 0; it < 16; it++) {
        int u = tid + it * 256;              // 0..4095 float4s
        int row = u >> 4;
        int q = u & 15;
        float4 v = *(const float4*)(z + (size_t)(m0 + row) * D_DIM + q * 4);
        float vv[4] = {v.x, v.y, v.z, v.w};
        uint32_t hp[2], lp[2];
        float zl2 = 0.f;
#pragma unroll
        for (int pr = 0; pr < 2; pr++) {
            __nv_bfloat16 h0 = __float2bfloat16(vv[2 * pr]);
            __nv_bfloat16 h1 = __float2bfloat16(vv[2 * pr + 1]);
            float lf0 = vv[2 * pr] - __bfloat162float(h0);
            float lf1 = vv[2 * pr + 1] - __bfloat162float(h1);
            zl2 += lf0 * lf0 + lf1 * lf1;
            __nv_bfloat16 l0 = __float2bfloat16(lf0);
            __nv_bfloat16 l1 = __float2bfloat16(lf1);
            __nv_bfloat162 hh = {h0, h1}, ll = {l0, l1};
            hp[pr] = *(uint32_t*)&hh;
            lp[pr] = *(uint32_t*)&ll;
        }
        // width-16 deterministic reduce of zl2 (16 threads share a row)
#pragma unroll
        for (int off = 8; off >= 1; off >>= 1)
            zl2 += __shfl_down_sync(0xffffffffu, zl2, off, 16);
        if ((tid & 15) == 0) zln2[row] = zl2;

        char* base = smem + SM_A + row * RSTRIDE;
        int c = q * 4;
#pragma unroll
        for (int pr = 0; pr < 2; pr++) {
            int cc = c + 2 * pr;
            *(uint32_t*)(base + cc * 2) = hp[pr];
            *(uint32_t*)(base + (cc + 64) * 2) = hp[pr];
            *(uint32_t*)(base + (cc + 128) * 2) = lp[pr];
        }
    }

    // ---- ldmatrix lane address offsets (bytes) ----
    uint32_t aoff[4];
#pragma unroll
    for (int i = 0; i < 4; i++)
        aoff[i] = sb + SM_A + (wm + i * 16 + (lane & 15)) * RSTRIDE + ((lane >> 4) * 16);
    uint32_t boff[4];
#pragma unroll
    for (int jj = 0; jj < 4; jj++)
        boff[jj] = (uint32_t)((wn + jj * 16 + ((lane >> 4) * 8) + (lane & 7)) * RSTRIDE +
                              (((lane >> 3) & 1) * 16));

    float bv[8], sv[8];
    int bi[8];
#pragma unroll
    for (int s = 0; s < 8; s++) { bv[s] = CUDART_INF_F; sv[s] = CUDART_INF_F; bi[s] = 0; }

    CP_WAIT0();
    __syncthreads();

    const char* BgB = (const char*)g_Bg;
    for (int ch = 0; ch < NCHUNKS; ch++) {
        // prefetch next chunk into other buffer (that buffer's readers synced out)
        if (ch < NCHUNKS - 1) {
            uint32_t dstb = sb + (((ch + 1) & 1) ? SM_B1 : SM_B0);
            const char* src = BgB + (size_t)(ch + 1) * BN * (KV * 2);
#pragma unroll
            for (int it = 0; it < 12; it++) {
                int u = tid + it * 256;
                int row = u / 24;
                int c16 = u - row * 24;
                CP16(dstb + row * RSTRIDE + c16 * 16,
                     src + (size_t)row * (KV * 2) + c16 * 16);
            }
            CP_COMMIT();
        }

        const uint32_t bbuf = sb + ((ch & 1) ? SM_B1 : SM_B0);
        float acc[4][8][4];
#pragma unroll
        for (int m = 0; m < 4; m++)
#pragma unroll
            for (int j = 0; j < 8; j++)
#pragma unroll
                for (int e = 0; e < 4; e++) acc[m][j][e] = 0.f;

#pragma unroll 4
        for (int k = 0; k < KSTEPS; k++) {
            uint32_t af[4][4], bf[4][4];
#pragma unroll
            for (int m = 0; m < 4; m++)
                LDSM4(af[m][0], af[m][1], af[m][2], af[m][3], aoff[m] + k * 32);
#pragma unroll
            for (int jj = 0; jj < 4; jj++)
                LDSM4(bf[jj][0], bf[jj][1], bf[jj][2], bf[jj][3],
                      bbuf + boff[jj] + k * 32);
#pragma unroll
            for (int m = 0; m < 4; m++)
#pragma unroll
                for (int j = 0; j < 8; j++)
                    MMA16816(acc[m][j], af[m], bf[j >> 1][(j & 1) * 2],
                             bf[j >> 1][(j & 1) * 2 + 1]);
        }

        // epilogue: dist = cnorm - 2*dot; track best/second per row-slot
        const int cb = ch * BN + wn;
#pragma unroll
        for (int j = 0; j < 8; j++) {
            int c0 = cb + j * 8 + 2 * (lane & 3);
            float cn0 = __ldg(g_cnorm + c0);
            float cn1 = __ldg(g_cnorm + c0 + 1);
#pragma unroll
            for (int m = 0; m < 4; m++) {
                float v00 = fmaf(-2.f, acc[m][j][0], cn0);
                float v01 = fmaf(-2.f, acc[m][j][1], cn1);
                float v10 = fmaf(-2.f, acc[m][j][2], cn0);
                float v11 = fmaf(-2.f, acc[m][j][3], cn1);
                int s0 = m * 2, s1 = m * 2 + 1;
                if (v00 < bv[s0]) { sv[s0] = bv[s0]; bv[s0] = v00; bi[s0] = c0; }
                else if (v00 < sv[s0]) sv[s0] = v00;
                if (v01 < bv[s0]) { sv[s0] = bv[s0]; bv[s0] = v01; bi[s0] = c0 + 1; }
                else if (v01 < sv[s0]) sv[s0] = v01;
                if (v10 < bv[s1]) { sv[s1] = bv[s1]; bv[s1] = v10; bi[s1] = c0; }
                else if (v10 < sv[s1]) sv[s1] = v10;
                if (v11 < bv[s1]) { sv[s1] = bv[s1]; bv[s1] = v11; bi[s1] = c0 + 1; }
                else if (v11 < sv[s1]) sv[s1] = v11;
            }
        }

        if (ch < NCHUNKS - 1) CP_WAIT0();
        __syncthreads();
    }

    // ---- quad reduce (lanes sharing a row: lane&3 = 0..3) ----
#pragma unroll
    for (int off = 1; off <= 2; off <<= 1) {
#pragma unroll
        for (int s = 0; s < 8; s++) {
            float ov = __shfl_xor_sync(0xffffffffu, bv[s], off);
            float os = __shfl_xor_sync(0xffffffffu, sv[s], off);
            int oi = __shfl_xor_sync(0xffffffffu, bi[s], off);
            if (ov < bv[s] || (ov == bv[s] && oi < bi[s])) {
                sv[s] = fminf(os, bv[s]);
                bv[s] = ov;
                bi[s] = oi;
            } else {
                sv[s] = fminf(sv[s], ov);
            }
        }
    }

    // ---- cross-warp (N-band) merge via smem scratch (reuse B0 region) ----
    float* mvS = (float*)(smem + SM_B0);
    float* msS = mvS + 512;
    int* miS = (int*)(msS + 512);
    if ((lane & 3) == 0) {
#pragma unroll
        for (int s = 0; s < 8; s++) {
            int gr = wm + (s >> 1) * 16 + (s & 1) * 8 + (lane >> 2);  // 0..255
            int idx = nband * 256 + gr;
            mvS[idx] = bv[s];
            msS[idx] = sv[s];
            miS[idx] = bi[s];
        }
    }
    __syncthreads();
    {
        int gr = tid;
        float b0v = mvS[gr], s0v = msS[gr];
        int b0i = miS[gr];
        float b1v = mvS[256 + gr], s1v = msS[256 + gr];
        int b1i = miS[256 + gr];
        float b, s2;
        int biF;
        if (b1v < b0v || (b1v == b0v && b1i < b0i)) {
            b = b1v; biF = b1i; s2 = fminf(s1v, b0v);
        } else {
            b = b0v; biF = b0i; s2 = fminf(s0v, b1v);
        }
        int row = m0 + gr;
        g_besti[row] = biF;
        float thr = 2.f * sqrtf(zln2[gr] * __uint_as_float(g_maxcl2)) + ACCSLACK;
        if (s2 - b <= thr) {
            int slot = atomicAdd(&g_nflag, 1);
            g_flags[slot] = row;
        }
    }
}

// ---------------------------------------------------------------------------
// K3: exact fp32 re-scan for ambiguous rows (vectorized)
// ---------------------------------------------------------------------------
__global__ __launch_bounds__(256) void fallback_kernel(const float* __restrict__ z,
                                                       const float* __restrict__ cb) {
    __shared__ float4 zr4[D_DIM / 4];
    __shared__ float rv[256];
    __shared__ int ri[256];
    const int tid = threadIdx.x;
    const int nf = g_nflag;
    for (int f = blockIdx.x; f < nf; f += gridDim.x) {
        int row = g_flags[f];
        if (tid < D_DIM / 4)
            zr4[tid] = *(const float4*)(z + (size_t)row * D_DIM + tid * 4);
        __syncthreads();
        float bvv = CUDART_INF_F;
        int bii = 0;
#pragma unroll 2
        for (int kk = 0; kk < K_CODES / 256; kk++) {
            int k = tid + kk * 256;
            const float4* c4 = (const float4*)(cb + (size_t)k * D_DIM);
            float d0 = 0.f, d1 = 0.f, d2 = 0.f, d3 = 0.f;
#pragma unroll
            for (int q = 0; q < 16; q += 4) {
                float4 a0 = c4[q], a1 = c4[q + 1], a2 = c4[q + 2], a3 = c4[q + 3];
                float4 z0 = zr4[q], z1 = zr4[q + 1], z2 = zr4[q + 2], z3 = zr4[q + 3];
                d0 = fmaf(a0.x, z0.x, fmaf(a0.y, z0.y, fmaf(a0.z, z0.z, fmaf(a0.w, z0.w, d0))));
                d1 = fmaf(a1.x, z1.x, fmaf(a1.y, z1.y, fmaf(a1.z, z1.z, fmaf(a1.w, z1.w, d1))));
                d2 = fmaf(a2.x, z2.x, fmaf(a2.y, z2.y, fmaf(a2.z, z2.z, fmaf(a2.w, z2.w, d2))));
                d3 = fmaf(a3.x, z3.x, fmaf(a3.y, z3.y, fmaf(a3.z, z3.z, fmaf(a3.w, z3.w, d3))));
            }
            float dot = (d0 + d1) + (d2 + d3);
            float d = fmaf(-2.f, dot, g_cnorm[k]);
            if (d < bvv) { bvv = d; bii = k; }
        }
        rv[tid] = bvv;
        ri[tid] = bii;
        __syncthreads();
        for (int s = 128; s > 0; s >>= 1) {
            if (tid < s) {
                float ov = rv[tid + s];
                int oi = ri[tid + s];
                if (ov < rv[tid] || (ov == rv[tid] && oi < ri[tid])) {
                    rv[tid] = ov;
                    ri[tid] = oi;
                }
            }
            __syncthreads();
        }
        if (tid == 0) g_besti[row] = ri[0];
        __syncthreads();
    }
}

// ---------------------------------------------------------------------------
// K4: outputs — gather codes, indices, commit partials
// ---------------------------------------------------------------------------
__global__ __launch_bounds__(256) void output_kernel(const float* __restrict__ z,
                                                     const float* __restrict__ cb,
                                                     float* __restrict__ out) {
    __shared__ float red[256];
    const int tid = threadIdx.x;
    const int m0 = blockIdx.x * 64;
    float lsum = 0.f;
#pragma unroll
    for (int it = 0; it < 16; it++) {
        int e = tid + it * 256;
        int row = e >> 6;
        int d = e & 63;
        int ci = g_besti[m0 + row];
        float cv = __ldg(cb + (size_t)ci * D_DIM + d);
        float zv = z[(size_t)(m0 + row) * D_DIM + d];
        float diff = cv - zv;
        lsum += diff * diff;
        out[(size_t)(m0 + row) * D_DIM + d] = cv;
    }
    if (tid < 64) out[CODES_ELEMS + m0 + tid] = (float)g_besti[m0 + tid];
    red[tid] = lsum;
    __syncthreads();
#pragma unroll
    for (int s = 128; s > 0; s >>= 1) {
        if (tid < s) red[tid] += red[tid + s];
        __syncthreads();
    }
    if (tid == 0) g_partials[blockIdx.x] = red[0];
}

// ---------------------------------------------------------------------------
// K5: deterministic commit-loss reduction
// ---------------------------------------------------------------------------
__global__ void final_kernel(float* __restrict__ out) {
    __shared__ double dred[256];
    int tid = threadIdx.x;
    double s = 0.0;
    for (int i = tid; i < OUTBLOCKS; i += 256) s += (double)g_partials[i];
    dred[tid] = s;
    __syncthreads();
#pragma unroll
    for (int st = 128; st > 0; st >>= 1) {
        if (tid < st) dred[tid] += dred[tid + st];
        __syncthreads();
    }
    if (tid == 0)
        out[CODES_ELEMS + NVEC] = (float)(dred[0] / (double)CODES_ELEMS);
}

// K6: no-op — pads the launch cycle to 7 so ncu's captured slot (#10) lands
// on vq_mma_kernel next profile.
__global__ void noop_kernel() {}

// ---------------------------------------------------------------------------
extern "C" void kernel_launch(void* const* d_in, const int* in_sizes, int n_in,
                              void* d_out, int out_size) {
    const float* z = (const float*)d_in[0];
    const float* cb = (const float*)d_in[1];
    if (n_in >= 2 && in_sizes[0] < in_sizes[1]) {
        const float* t = z; z = cb; cb = t;
    }
    float* out = (float*)d_out;

    cudaFuncSetAttribute(vq_mma_kernel,
                         cudaFuncAttributeMaxDynamicSharedMemorySize, SMEM_K2);

    reset_kernel<<<1, 1>>>();
    prep_kernel<<<(K_CODES + 255) / 256, 256>>>(cb);
    vq_mma_kernel<<<NCTAS, 256, SMEM_K2>>>(z);
    fallback_kernel<<<256, 256>>>(z, cb);
    output_kernel<<<OUTBLOCKS, 256>>>(z, cb, out);
    final_kernel<<<1, 256>>>(out);
    noop_kernel<<<1, 32>>>();
}

// round 7
// speedup vs baseline: 3.1410x; 1.4041x over previous
#include <cuda_runtime.h>
#include <cuda_bf16.h>
#include <math_constants.h>
#include <cstdint>

#define D_DIM 64
#define K_CODES 2048
#define NVEC 131072
#define CODES_ELEMS (NVEC * D_DIM)
#define MTILE 128                    // rows per CTA
#define BN 64                        // codes per chunk
#define NCHUNKS (K_CODES / BN)       // 32
#define KV 192                       // virtual K: zh*ch + zh*cl + zl*ch
#define KSTEPS (KV / 16)             // 12
#define NCTAS (NVEC / MTILE)         // 1024
#define OUTBLOCKS 2048
#define ACCSLACK 3e-3f

#define RSTRIDE 400                  // bytes per K-row (384 pad to 400 -> ldsm conflict-free)
#define SM_A 0                       // 128*400 = 51200
#define SM_B0 51200                  // 64*400 = 25600
#define SM_B1 76800
#define SM_ZLN 102400                // 128 floats
#define SMEM_K2 102912

__device__ __align__(16) __nv_bfloat16 g_Bg[K_CODES * KV];  // packed codebook [ch|cl|ch]
__device__ float g_cnorm[K_CODES];
__device__ unsigned int g_maxcl2;
__device__ int g_besti[NVEC];
__device__ int g_flags[NVEC];
__device__ int g_nflag;
__device__ float g_partials[OUTBLOCKS];

// ---------------- PTX helpers (base-sm_103 legal) ----------------
__device__ __forceinline__ uint32_t smem_u32(const void* p) {
    uint32_t a;
    asm("{ .reg .u64 t; cvta.to.shared.u64 t, %1; cvt.u32.u64 %0, t; }"
        : "=r"(a) : "l"(p));
    return a;
}
#define CP16(dst, src) \
    asm volatile("cp.async.cg.shared.global [%0], [%1], 16;" :: "r"(dst), "l"(src))
#define CP_COMMIT() asm volatile("cp.async.commit_group;" ::: "memory")
#define CP_WAIT0() asm volatile("cp.async.wait_group 0;" ::: "memory")

#define LDSM4(r0, r1, r2, r3, addr)                                         \
    asm volatile("ldmatrix.sync.aligned.m8n8.x4.shared.b16 {%0,%1,%2,%3},[%4];" \
                 : "=r"(r0), "=r"(r1), "=r"(r2), "=r"(r3) : "r"(addr))

#define MMA16816(c, a, b0, b1)                                              \
    asm volatile(                                                           \
        "mma.sync.aligned.m16n8k16.row.col.f32.bf16.bf16.f32 "              \
        "{%0,%1,%2,%3},{%4,%5,%6,%7},{%8,%9},{%0,%1,%2,%3};"                \
        : "+f"((c)[0]), "+f"((c)[1]), "+f"((c)[2]), "+f"((c)[3])            \
        : "r"((a)[0]), "r"((a)[1]), "r"((a)[2]), "r"((a)[3]),               \
          "r"(b0), "r"(b1))

// ---------------------------------------------------------------------------
__global__ void reset_kernel() { g_nflag = 0; g_maxcl2 = 0u; }

// ---------------------------------------------------------------------------
// prep: cnorm + packed split codebook [ch | cl | ch] + max ||cl||^2
// ---------------------------------------------------------------------------
__global__ void prep_kernel(const float* __restrict__ cb) {
    int n = blockIdx.x * blockDim.x + threadIdx.x;
    if (n >= K_CODES) return;
    const float4* row = (const float4*)(cb + (size_t)n * D_DIM);
    float s = 0.f, cl2 = 0.f;
    __nv_bfloat16* bg = g_Bg + (size_t)n * KV;
#pragma unroll
    for (int i = 0; i < D_DIM / 4; i++) {
        float4 v = row[i];
        s += v.x * v.x + v.y * v.y + v.z * v.z + v.w * v.w;
        float vv[4] = {v.x, v.y, v.z, v.w};
#pragma unroll
        for (int j = 0; j < 4; j++) {
            int d = i * 4 + j;
            __nv_bfloat16 h = __float2bfloat16(vv[j]);
            float lf = vv[j] - __bfloat162float(h);
            __nv_bfloat16 l = __float2bfloat16(lf);
            cl2 += lf * lf;
            bg[d] = h;
            bg[64 + d] = l;
            bg[128 + d] = h;
        }
    }
    g_cnorm[n] = s;
    atomicMax(&g_maxcl2, __float_as_uint(cl2));
}

// ---------------------------------------------------------------------------
// vq: HMMA distance GEMM + argmin(best,second) + flags.  2 CTAs/SM.
// ---------------------------------------------------------------------------
__global__ __launch_bounds__(256, 2) void vq_mma_kernel(const float* __restrict__ z) {
    extern __shared__ char smem[];
    const uint32_t sb = smem_u32(smem);
    const int tid = threadIdx.x;
    const int wid = tid >> 5;
    const int lane = tid & 31;
    const int mband = wid >> 1;      // 0..3 -> rows mband*32 .. +31
    const int nband = wid & 1;       // 0..1 -> cols nband*32 .. +31 of each chunk
    const int wm = mband * 32;
    const int wn = nband * 32;
    const int m0 = blockIdx.x * MTILE;
    float* zln2 = (float*)(smem + SM_ZLN);

    // ---- issue chunk-0 B load first (overlaps A fill) ----
    {
        const char* src0 = (const char*)g_Bg;
#pragma unroll
        for (int it = 0; it < 6; it++) {
            int u = tid + it * 256;          // 0..1535
            int row = u / 24;
            int c16 = u - row * 24;
            CP16(sb + SM_B0 + row * RSTRIDE + c16 * 16,
                 src0 + (size_t)row * (KV * 2) + c16 * 16);
        }
        CP_COMMIT();
    }

    // ---- A fill: z rows -> bf16 split [zh | zh | zl], + per-row ||zl||^2 ----
#pragma unroll
    for (int it = 0; it < 8; it++) {
        int u = tid + it * 256;              // 0..2047 float4s
        int row = u >> 4;                    // 0..127
        int q = u & 15;
        float4 v = *(const float4*)(z + (size_t)(m0 + row) * D_DIM + q * 4);
        float vv[4] = {v.x, v.y, v.z, v.w};
        uint32_t hp[2], lp[2];
        float zl2 = 0.f;
#pragma unroll
        for (int pr = 0; pr < 2; pr++) {
            __nv_bfloat16 h0 = __float2bfloat16(vv[2 * pr]);
            __nv_bfloat16 h1 = __float2bfloat16(vv[2 * pr + 1]);
            float lf0 = vv[2 * pr] - __bfloat162float(h0);
            float lf1 = vv[2 * pr + 1] - __bfloat162float(h1);
            zl2 += lf0 * lf0 + lf1 * lf1;
            __nv_bfloat16 l0 = __float2bfloat16(lf0);
            __nv_bfloat16 l1 = __float2bfloat16(lf1);
            __nv_bfloat162 hh = {h0, h1}, ll = {l0, l1};
            hp[pr] = *(uint32_t*)&hh;
            lp[pr] = *(uint32_t*)&ll;
        }
#pragma unroll
        for (int off = 8; off >= 1; off >>= 1)
            zl2 += __shfl_down_sync(0xffffffffu, zl2, off, 16);
        if ((tid & 15) == 0) zln2[row] = zl2;

        char* base = smem + SM_A + row * RSTRIDE;
        int c = q * 4;
#pragma unroll
        for (int pr = 0; pr < 2; pr++) {
            int cc = c + 2 * pr;
            *(uint32_t*)(base + cc * 2) = hp[pr];
            *(uint32_t*)(base + (cc + 64) * 2) = hp[pr];
            *(uint32_t*)(base + (cc + 128) * 2) = lp[pr];
        }
    }

    // ---- ldmatrix lane offsets ----
    uint32_t aoff[2];
#pragma unroll
    for (int i = 0; i < 2; i++)
        aoff[i] = sb + SM_A + (wm + i * 16 + (lane & 15)) * RSTRIDE + ((lane >> 4) * 16);
    uint32_t boff[2];
#pragma unroll
    for (int jj = 0; jj < 2; jj++)
        boff[jj] = (uint32_t)((wn + jj * 16 + ((lane >> 4) * 8) + (lane & 7)) * RSTRIDE +
                              (((lane >> 3) & 1) * 16));

    float bv[4], sv[4];
    int bi[4];
#pragma unroll
    for (int s = 0; s < 4; s++) { bv[s] = CUDART_INF_F; sv[s] = CUDART_INF_F; bi[s] = 0; }

    CP_WAIT0();
    __syncthreads();

    const char* BgB = (const char*)g_Bg;
    for (int ch = 0; ch < NCHUNKS; ch++) {
        if (ch < NCHUNKS - 1) {
            uint32_t dstb = sb + (((ch + 1) & 1) ? SM_B1 : SM_B0);
            const char* src = BgB + (size_t)(ch + 1) * BN * (KV * 2);
#pragma unroll
            for (int it = 0; it < 6; it++) {
                int u = tid + it * 256;
                int row = u / 24;
                int c16 = u - row * 24;
                CP16(dstb + row * RSTRIDE + c16 * 16,
                     src + (size_t)row * (KV * 2) + c16 * 16);
            }
            CP_COMMIT();
        }

        const uint32_t bbuf = sb + ((ch & 1) ? SM_B1 : SM_B0);
        float acc[2][4][4];
#pragma unroll
        for (int m = 0; m < 2; m++)
#pragma unroll
            for (int j = 0; j < 4; j++)
#pragma unroll
                for (int e = 0; e < 4; e++) acc[m][j][e] = 0.f;

#pragma unroll
        for (int k = 0; k < KSTEPS; k++) {
            uint32_t af[2][4], bf[2][4];
#pragma unroll
            for (int m = 0; m < 2; m++)
                LDSM4(af[m][0], af[m][1], af[m][2], af[m][3], aoff[m] + k * 32);
#pragma unroll
            for (int jj = 0; jj < 2; jj++)
                LDSM4(bf[jj][0], bf[jj][1], bf[jj][2], bf[jj][3],
                      bbuf + boff[jj] + k * 32);
#pragma unroll
            for (int m = 0; m < 2; m++)
#pragma unroll
                for (int j = 0; j < 4; j++)
                    MMA16816(acc[m][j], af[m], bf[j >> 1][(j & 1) * 2],
                             bf[j >> 1][(j & 1) * 2 + 1]);
        }

        // epilogue: dist = cnorm - 2*dot; best/second per row-slot
        const int cbase = ch * BN + wn;
#pragma unroll
        for (int j = 0; j < 4; j++) {
            int c0 = cbase + j * 8 + 2 * (lane & 3);
            float cn0 = __ldg(g_cnorm + c0);
            float cn1 = __ldg(g_cnorm + c0 + 1);
#pragma unroll
            for (int m = 0; m < 2; m++) {
                float v00 = fmaf(-2.f, acc[m][j][0], cn0);
                float v01 = fmaf(-2.f, acc[m][j][1], cn1);
                float v10 = fmaf(-2.f, acc[m][j][2], cn0);
                float v11 = fmaf(-2.f, acc[m][j][3], cn1);
                int s0 = m * 2, s1 = m * 2 + 1;
                if (v00 < bv[s0]) { sv[s0] = bv[s0]; bv[s0] = v00; bi[s0] = c0; }
                else if (v00 < sv[s0]) sv[s0] = v00;
                if (v01 < bv[s0]) { sv[s0] = bv[s0]; bv[s0] = v01; bi[s0] = c0 + 1; }
                else if (v01 < sv[s0]) sv[s0] = v01;
                if (v10 < bv[s1]) { sv[s1] = bv[s1]; bv[s1] = v10; bi[s1] = c0; }
                else if (v10 < sv[s1]) sv[s1] = v10;
                if (v11 < bv[s1]) { sv[s1] = bv[s1]; bv[s1] = v11; bi[s1] = c0 + 1; }
                else if (v11 < sv[s1]) sv[s1] = v11;
            }
        }

        if (ch < NCHUNKS - 1) CP_WAIT0();
        __syncthreads();
    }

    // ---- quad reduce (lanes sharing a row) ----
#pragma unroll
    for (int off = 1; off <= 2; off <<= 1) {
#pragma unroll
        for (int s = 0; s < 4; s++) {
            float ov = __shfl_xor_sync(0xffffffffu, bv[s], off);
            float os = __shfl_xor_sync(0xffffffffu, sv[s], off);
            int oi = __shfl_xor_sync(0xffffffffu, bi[s], off);
            if (ov < bv[s] || (ov == bv[s] && oi < bi[s])) {
                sv[s] = fminf(os, bv[s]);
                bv[s] = ov;
                bi[s] = oi;
            } else {
                sv[s] = fminf(sv[s], ov);
            }
        }
    }

    // ---- cross-warp (N-band) merge via smem scratch (reuse B0 region) ----
    float* mvS = (float*)(smem + SM_B0);
    float* msS = mvS + 256;
    int* miS = (int*)(msS + 256);
    if ((lane & 3) == 0) {
#pragma unroll
        for (int s = 0; s < 4; s++) {
            int gr = wm + (s >> 1) * 16 + (s & 1) * 8 + (lane >> 2);  // 0..127
            int idx = nband * 128 + gr;
            mvS[idx] = bv[s];
            msS[idx] = sv[s];
            miS[idx] = bi[s];
        }
    }
    __syncthreads();
    if (tid < 128) {
        int gr = tid;
        float b0v = mvS[gr], s0v = msS[gr];
        int b0i = miS[gr];
        float b1v = mvS[128 + gr], s1v = msS[128 + gr];
        int b1i = miS[128 + gr];
        float b, s2;
        int biF;
        if (b1v < b0v || (b1v == b0v && b1i < b0i)) {
            b = b1v; biF = b1i; s2 = fminf(s1v, b0v);
        } else {
            b = b0v; biF = b0i; s2 = fminf(s0v, b1v);
        }
        int row = m0 + gr;
        g_besti[row] = biF;
        float thr = 2.f * sqrtf(zln2[gr] * __uint_as_float(g_maxcl2)) + ACCSLACK;
        if (s2 - b <= thr) {
            int slot = atomicAdd(&g_nflag, 1);
            g_flags[slot] = row;
        }
    }
}

// ---------------------------------------------------------------------------
// fallback: exact fp32 re-scan for ambiguous rows (vectorized)
// ---------------------------------------------------------------------------
__global__ __launch_bounds__(256) void fallback_kernel(const float* __restrict__ z,
                                                       const float* __restrict__ cb) {
    __shared__ float4 zr4[D_DIM / 4];
    __shared__ float rv[256];
    __shared__ int ri[256];
    const int tid = threadIdx.x;
    const int nf = g_nflag;
    for (int f = blockIdx.x; f < nf; f += gridDim.x) {
        int row = g_flags[f];
        if (tid < D_DIM / 4)
            zr4[tid] = *(const float4*)(z + (size_t)row * D_DIM + tid * 4);
        __syncthreads();
        float bvv = CUDART_INF_F;
        int bii = 0;
#pragma unroll 2
        for (int kk = 0; kk < K_CODES / 256; kk++) {
            int k = tid + kk * 256;
            const float4* c4 = (const float4*)(cb + (size_t)k * D_DIM);
            float d0 = 0.f, d1 = 0.f, d2 = 0.f, d3 = 0.f;
#pragma unroll
            for (int q = 0; q < 16; q += 4) {
                float4 a0 = c4[q], a1 = c4[q + 1], a2 = c4[q + 2], a3 = c4[q + 3];
                float4 z0 = zr4[q], z1 = zr4[q + 1], z2 = zr4[q + 2], z3 = zr4[q + 3];
                d0 = fmaf(a0.x, z0.x, fmaf(a0.y, z0.y, fmaf(a0.z, z0.z, fmaf(a0.w, z0.w, d0))));
                d1 = fmaf(a1.x, z1.x, fmaf(a1.y, z1.y, fmaf(a1.z, z1.z, fmaf(a1.w, z1.w, d1))));
                d2 = fmaf(a2.x, z2.x, fmaf(a2.y, z2.y, fmaf(a2.z, z2.z, fmaf(a2.w, z2.w, d2))));
                d3 = fmaf(a3.x, z3.x, fmaf(a3.y, z3.y, fmaf(a3.z, z3.z, fmaf(a3.w, z3.w, d3))));
            }
            float dot = (d0 + d1) + (d2 + d3);
            float d = fmaf(-2.f, dot, g_cnorm[k]);
            if (d < bvv) { bvv = d; bii = k; }
        }
        rv[tid] = bvv;
        ri[tid] = bii;
        __syncthreads();
        for (int s = 128; s > 0; s >>= 1) {
            if (tid < s) {
                float ov = rv[tid + s];
                int oi = ri[tid + s];
                if (ov < rv[tid] || (ov == rv[tid] && oi < ri[tid])) {
                    rv[tid] = ov;
                    ri[tid] = oi;
                }
            }
            __syncthreads();
        }
        if (tid == 0) g_besti[row] = ri[0];
        __syncthreads();
    }
}

// ---------------------------------------------------------------------------
// output: gather codes, indices, commit partials
// ---------------------------------------------------------------------------
__global__ __launch_bounds__(256) void output_kernel(const float* __restrict__ z,
                                                     const float* __restrict__ cb,
                                                     float* __restrict__ out) {
    __shared__ float red[256];
    const int tid = threadIdx.x;
    const int m0 = blockIdx.x * 64;
    float lsum = 0.f;
#pragma unroll
    for (int it = 0; it < 16; it++) {
        int e = tid + it * 256;
        int row = e >> 6;
        int d = e & 63;
        int ci = g_besti[m0 + row];
        float cv = __ldg(cb + (size_t)ci * D_DIM + d);
        float zv = z[(size_t)(m0 + row) * D_DIM + d];
        float diff = cv - zv;
        lsum += diff * diff;
        out[(size_t)(m0 + row) * D_DIM + d] = cv;
    }
    if (tid < 64) out[CODES_ELEMS + m0 + tid] = (float)g_besti[m0 + tid];
    red[tid] = lsum;
    __syncthreads();
#pragma unroll
    for (int s = 128; s > 0; s >>= 1) {
        if (tid < s) red[tid] += red[tid + s];
        __syncthreads();
    }
    if (tid == 0) g_partials[blockIdx.x] = red[0];
}

// ---------------------------------------------------------------------------
__global__ void final_kernel(float* __restrict__ out) {
    __shared__ double dred[256];
    int tid = threadIdx.x;
    double s = 0.0;
    for (int i = tid; i < OUTBLOCKS; i += 256) s += (double)g_partials[i];
    dred[tid] = s;
    __syncthreads();
#pragma unroll
    for (int st = 128; st > 0; st >>= 1) {
        if (tid < st) dred[tid] += dred[tid + st];
        __syncthreads();
    }
    if (tid == 0)
        out[CODES_ELEMS + NVEC] = (float)(dred[0] / (double)CODES_ELEMS);
}

// noop at launch index 2: puts vq_mma at index 3 = ncu's captured slot (L=45,
// 45 mod 7 == 3).
__global__ void noop_kernel() {}

// ---------------------------------------------------------------------------
extern "C" void kernel_launch(void* const* d_in, const int* in_sizes, int n_in,
                              void* d_out, int out_size) {
    const float* z = (const float*)d_in[0];
    const float* cb = (const float*)d_in[1];
    if (n_in >= 2 && in_sizes[0] < in_sizes[1]) {
        const float* t = z; z = cb; cb = t;
    }
    float* out = (float*)d_out;

    cudaFuncSetAttribute(vq_mma_kernel,
                         cudaFuncAttributeMaxDynamicSharedMemorySize, SMEM_K2);

    reset_kernel<<<1, 1>>>();                              // 0
    prep_kernel<<<(K_CODES + 255) / 256, 256>>>(cb);       // 1
    noop_kernel<<<1, 32>>>();                              // 2
    vq_mma_kernel<<<NCTAS, 256, SMEM_K2>>>(z);             // 3  <- profiled slot
    fallback_kernel<<<256, 256>>>(z, cb);                  // 4
    output_kernel<<<OUTBLOCKS, 256>>>(z, cb, out);         // 5
    final_kernel<<<1, 256>>>(out);                         // 6
}

// round 10
// speedup vs baseline: 3.3608x; 1.0700x over previous
#include <cuda_runtime.h>
#include <cuda_bf16.h>
#include <math_constants.h>
#include <cstdint>

#define D_DIM 64
#define K_CODES 2048
#define NVEC 131072
#define CODES_ELEMS (NVEC * D_DIM)
#define MTILE 128
#define BN 64
#define NCHUNKS (K_CODES / BN)       // 32
#define NCTAS (NVEC / MTILE)         // 1024
#define OUTBLOCKS 2048
#define SCORESLACK 2e-3f

#define BCOLS 144                    // [ch(64) | cl(64) | cnh cnl | 0 x14]
#define BROW_G (BCOLS * 2)           // 288 bytes per g_Bg row
#define RSTRIDE 304                  // smem row stride (288 + 16 pad; 304%128=48 -> conflict-free)
#define SM_A 0                       // 128*304 = 38912
#define SM_B0 38912                  // 64*304 = 19456
#define SM_B1 58368
#define SM_ZLN 77824                 // 128 floats
#define SMEM_K2 78336

__device__ __align__(16) __nv_bfloat16 g_Bg[K_CODES * BCOLS];
__device__ float g_cnorm[K_CODES];
__device__ unsigned int g_maxcl2;
__device__ int g_besti[NVEC];
__device__ int g_flags[NVEC];
__device__ int g_nflag;
__device__ float g_partials[OUTBLOCKS];

// ---------------- PTX helpers (base-sm_103 legal) ----------------
__device__ __forceinline__ uint32_t smem_u32(const void* p) {
    uint32_t a;
    asm("{ .reg .u64 t; cvta.to.shared.u64 t, %1; cvt.u32.u64 %0, t; }"
        : "=r"(a) : "l"(p));
    return a;
}
#define CP16(dst, src) \
    asm volatile("cp.async.cg.shared.global [%0], [%1], 16;" :: "r"(dst), "l"(src))
#define CP_COMMIT() asm volatile("cp.async.commit_group;" ::: "memory")
#define CP_WAIT0() asm volatile("cp.async.wait_group 0;" ::: "memory")

#define LDSM4(r0, r1, r2, r3, addr)                                         \
    asm volatile("ldmatrix.sync.aligned.m8n8.x4.shared.b16 {%0,%1,%2,%3},[%4];" \
                 : "=r"(r0), "=r"(r1), "=r"(r2), "=r"(r3) : "r"(addr))

#define MMA16816(c, a, b0, b1)                                              \
    asm volatile(                                                           \
        "mma.sync.aligned.m16n8k16.row.col.f32.bf16.bf16.f32 "              \
        "{%0,%1,%2,%3},{%4,%5,%6,%7},{%8,%9},{%0,%1,%2,%3};"                \
        : "+f"((c)[0]), "+f"((c)[1]), "+f"((c)[2]), "+f"((c)[3])            \
        : "r"((a)[0]), "r"((a)[1]), "r"((a)[2]), "r"((a)[3]),               \
          "r"(b0), "r"(b1))

#define MMA16816_INIT(c, a, b0, b1)                                         \
    asm volatile(                                                           \
        "mma.sync.aligned.m16n8k16.row.col.f32.bf16.bf16.f32 "              \
        "{%0,%1,%2,%3},{%4,%5,%6,%7},{%8,%9},{%10,%10,%10,%10};"            \
        : "=f"((c)[0]), "=f"((c)[1]), "=f"((c)[2]), "=f"((c)[3])            \
        : "r"((a)[0]), "r"((a)[1]), "r"((a)[2]), "r"((a)[3]),               \
          "r"(b0), "r"(b1), "f"(0.f))

// ---------------------------------------------------------------------------
__global__ void reset_kernel() { g_nflag = 0; g_maxcl2 = 0u; }

// ---------------------------------------------------------------------------
// prep: packed codebook [ch | cl | split(-cn/2) | zeros] + cnorm + max||cl||^2
// ---------------------------------------------------------------------------
__global__ void prep_kernel(const float* __restrict__ cb) {
    int n = blockIdx.x * blockDim.x + threadIdx.x;
    if (n >= K_CODES) return;
    const float4* row = (const float4*)(cb + (size_t)n * D_DIM);
    float s = 0.f, cl2 = 0.f;
    __nv_bfloat16* bg = g_Bg + (size_t)n * BCOLS;
#pragma unroll
    for (int i = 0; i < D_DIM / 4; i++) {
        float4 v = row[i];
        s += v.x * v.x + v.y * v.y + v.z * v.z + v.w * v.w;
        float vv[4] = {v.x, v.y, v.z, v.w};
#pragma unroll
        for (int j = 0; j < 4; j++) {
            int d = i * 4 + j;
            __nv_bfloat16 h = __float2bfloat16(vv[j]);
            float lf = vv[j] - __bfloat162float(h);
            __nv_bfloat16 l = __float2bfloat16(lf);
            cl2 += lf * lf;
            bg[d] = h;
            bg[64 + d] = l;
        }
    }
    float half_neg = -0.5f * s;
    __nv_bfloat16 cnh = __float2bfloat16(half_neg);
    __nv_bfloat16 cnl = __float2bfloat16(half_neg - __bfloat162float(cnh));
    bg[128] = cnh;
    bg[129] = cnl;
#pragma unroll
    for (int t = 130; t < BCOLS; t++) bg[t] = __float2bfloat16(0.f);
    g_cnorm[n] = s;
    atomicMax(&g_maxcl2, __float_as_uint(cl2));
}

// ---------------------------------------------------------------------------
// vq: HMMA score GEMM (score = dot - cn/2 folded in) + packed argmax
// ---------------------------------------------------------------------------
__global__ __launch_bounds__(256, 2) void vq_mma_kernel(const float* __restrict__ z) {
    extern __shared__ char smem[];
    const uint32_t sb = smem_u32(smem);
    const int tid = threadIdx.x;
    const int wid = tid >> 5;
    const int lane = tid & 31;
    const int mband = wid >> 1;
    const int nband = wid & 1;
    const int wm = mband * 32;
    const int wn = nband * 32;
    const int m0 = blockIdx.x * MTILE;
    float* zln2 = (float*)(smem + SM_ZLN);

    // ---- issue chunk-0 B load (no-division scheme: 4 threads per row) ----
    const char* BgB = (const char*)g_Bg;
    {
        int r = tid >> 2;            // 0..63
        int c0 = (tid & 3) * 5;      // unit base
#pragma unroll
        for (int q = 0; q < 5; q++) {
            int c = c0 + q;
            if (c < 18)
                CP16(sb + SM_B0 + r * RSTRIDE + c * 16,
                     BgB + (size_t)r * BROW_G + c * 16);
        }
        CP_COMMIT();
    }

    // ---- A fill: [zh | zl | ones | zeros] + per-row ||zl||^2 ----
#pragma unroll
    for (int it = 0; it < 8; it++) {
        int u = tid + it * 256;              // 0..2047 float4s
        int row = u >> 4;
        int q = u & 15;
        float4 v = *(const float4*)(z + (size_t)(m0 + row) * D_DIM + q * 4);
        float vv[4] = {v.x, v.y, v.z, v.w};
        uint32_t hp[2], lp[2];
        float zl2 = 0.f;
#pragma unroll
        for (int pr = 0; pr < 2; pr++) {
            __nv_bfloat16 h0 = __float2bfloat16(vv[2 * pr]);
            __nv_bfloat16 h1 = __float2bfloat16(vv[2 * pr + 1]);
            float lf0 = vv[2 * pr] - __bfloat162float(h0);
            float lf1 = vv[2 * pr + 1] - __bfloat162float(h1);
            zl2 += lf0 * lf0 + lf1 * lf1;
            __nv_bfloat16 l0 = __float2bfloat16(lf0);
            __nv_bfloat16 l1 = __float2bfloat16(lf1);
            __nv_bfloat162 hh = {h0, h1}, ll = {l0, l1};
            hp[pr] = *(uint32_t*)&hh;
            lp[pr] = *(uint32_t*)&ll;
        }
#pragma unroll
        for (int off = 8; off >= 1; off >>= 1)
            zl2 += __shfl_down_sync(0xffffffffu, zl2, off, 16);
        if ((tid & 15) == 0) zln2[row] = zl2;

        char* base = smem + SM_A + row * RSTRIDE;
        int c = q * 4;
#pragma unroll
        for (int pr = 0; pr < 2; pr++) {
            int cc = c + 2 * pr;
            *(uint32_t*)(base + cc * 2) = hp[pr];            // zh
            *(uint32_t*)(base + 128 + cc * 2) = lp[pr];      // zl
        }
    }
    if (tid < MTILE) {
        char* base = smem + SM_A + tid * RSTRIDE;
        __nv_bfloat162 one = {__float2bfloat16(1.f), __float2bfloat16(1.f)};
        *(uint32_t*)(base + 256) = *(uint32_t*)&one;         // ones cols 128-129
#pragma unroll
        for (int w = 0; w < 7; w++) *(uint32_t*)(base + 260 + w * 4) = 0u;
    }

    // ---- lane base offsets ----
    uint32_t aoffb[2];
#pragma unroll
    for (int i = 0; i < 2; i++)
        aoffb[i] = sb + SM_A + (wm + i * 16 + (lane & 15)) * RSTRIDE + ((lane >> 4) * 16);
    uint32_t boffb[2];
#pragma unroll
    for (int jj = 0; jj < 2; jj++)
        boffb[jj] = (uint32_t)((wn + jj * 16 + ((lane >> 4) * 8) + (lane & 7)) * RSTRIDE +
                               (((lane >> 3) & 1) * 16));

    float bv[4], sv[4];
    int bi[4];
#pragma unroll
    for (int s = 0; s < 4; s++) { bv[s] = -CUDART_INF_F; sv[s] = -CUDART_INF_F; bi[s] = 0; }

    CP_WAIT0();
    __syncthreads();

    // hoisted constant ext a-frags (ones columns)
    uint32_t a_ext[2][4];
#pragma unroll
    for (int m = 0; m < 2; m++)
        LDSM4(a_ext[m][0], a_ext[m][1], a_ext[m][2], a_ext[m][3], aoffb[m] + 256);

    for (int ch = 0; ch < NCHUNKS; ch++) {
        if (ch < NCHUNKS - 1) {
            uint32_t dstb = sb + (((ch + 1) & 1) ? SM_B1 : SM_B0);
            const char* src = BgB + (size_t)(ch + 1) * BN * BROW_G;
            int r = tid >> 2;
            int c0 = (tid & 3) * 5;
#pragma unroll
            for (int q = 0; q < 5; q++) {
                int c = c0 + q;
                if (c < 18)
                    CP16(dstb + r * RSTRIDE + c * 16, src + (size_t)r * BROW_G + c * 16);
            }
            CP_COMMIT();
        }

        const uint32_t bbuf = sb + ((ch & 1) ? SM_B1 : SM_B0);
        float acc[2][4][4];

#pragma unroll
        for (int kk = 0; kk < 4; kk++) {
            uint32_t azh[2][4], azl[2][4], bch[2][4], bcl[2][4];
#pragma unroll
            for (int m = 0; m < 2; m++) {
                LDSM4(azh[m][0], azh[m][1], azh[m][2], azh[m][3], aoffb[m] + kk * 32);
                LDSM4(azl[m][0], azl[m][1], azl[m][2], azl[m][3], aoffb[m] + 128 + kk * 32);
            }
#pragma unroll
            for (int jj = 0; jj < 2; jj++) {
                LDSM4(bch[jj][0], bch[jj][1], bch[jj][2], bch[jj][3],
                      bbuf + boffb[jj] + kk * 32);
                LDSM4(bcl[jj][0], bcl[jj][1], bcl[jj][2], bcl[jj][3],
                      bbuf + boffb[jj] + 128 + kk * 32);
            }
#pragma unroll
            for (int m = 0; m < 2; m++)
#pragma unroll
                for (int j = 0; j < 4; j++) {
                    uint32_t* bc = &bch[j >> 1][(j & 1) * 2];
                    uint32_t* bl = &bcl[j >> 1][(j & 1) * 2];
                    if (kk == 0) {
                        MMA16816_INIT(acc[m][j], azh[m], bc[0], bc[1]);
                    } else {
                        MMA16816(acc[m][j], azh[m], bc[0], bc[1]);
                    }
                    MMA16816(acc[m][j], azl[m], bc[0], bc[1]);
                    MMA16816(acc[m][j], azh[m], bl[0], bl[1]);
                }
        }
        // ext k-slice: + (-cn/2)
        {
            uint32_t bex[2][4];
#pragma unroll
            for (int jj = 0; jj < 2; jj++)
                LDSM4(bex[jj][0], bex[jj][1], bex[jj][2], bex[jj][3],
                      bbuf + boffb[jj] + 256);
#pragma unroll
            for (int m = 0; m < 2; m++)
#pragma unroll
                for (int j = 0; j < 4; j++) {
                    uint32_t* be = &bex[j >> 1][(j & 1) * 2];
                    MMA16816(acc[m][j], a_ext[m], be[0], be[1]);
                }
        }

        // ---- packed argmax epilogue (log-depth, no index chains) ----
#pragma unroll
        for (int m = 0; m < 2; m++)
#pragma unroll
            for (int half = 0; half < 2; half++) {
                const int s = m * 2 + half;
                float p_[8];
#pragma unroll
                for (int j = 0; j < 4; j++)
#pragma unroll
                    for (int b = 0; b < 2; b++) {
                        int cand = j * 2 + b;
                        uint32_t ivb = (__float_as_uint(acc[m][j][half * 2 + b]) &
                                        0xFFFFFFF8u) | (uint32_t)(7 - cand);
                        p_[cand] = __uint_as_float(ivb);
                    }
                float M01 = fmaxf(p_[0], p_[1]), m01 = fminf(p_[0], p_[1]);
                float M23 = fmaxf(p_[2], p_[3]), m23 = fminf(p_[2], p_[3]);
                float M45 = fmaxf(p_[4], p_[5]), m45 = fminf(p_[4], p_[5]);
                float M67 = fmaxf(p_[6], p_[7]), m67 = fminf(p_[6], p_[7]);
                float Ma = fmaxf(M01, M23);
                float sa = fmaxf(fminf(M01, M23), fmaxf(m01, m23));
                float Mb = fmaxf(M45, M67);
                float sb2 = fmaxf(fminf(M45, M67), fmaxf(m45, m67));
                float M = fmaxf(Ma, Mb);
                float S = fmaxf(fminf(Ma, Mb), fmaxf(sa, sb2));
                bool p = M > bv[s];
                int pk = (int)(__float_as_uint(M) & 7u);
                bi[s] = p ? ((ch << 3) | pk) : bi[s];
                sv[s] = p ? fmaxf(bv[s], S) : fmaxf(sv[s], M);
                bv[s] = p ? M : bv[s];
            }

        if (ch < NCHUNKS - 1) CP_WAIT0();
        __syncthreads();
    }

    // ---- decode per-slot candidate index ----
    const int cq2 = 2 * (lane & 3);
    int ci[4];
#pragma unroll
    for (int s = 0; s < 4; s++) {
        int cand = 7 - (bi[s] & 7);
        ci[s] = (bi[s] >> 3) * BN + wn + ((cand >> 1) << 3) + (cand & 1) + cq2;
    }

    // ---- quad reduce across lane&3 (same row, different col groups) ----
#pragma unroll
    for (int off = 1; off <= 2; off <<= 1) {
#pragma unroll
        for (int s = 0; s < 4; s++) {
            float ov = __shfl_xor_sync(0xffffffffu, bv[s], off);
            float os = __shfl_xor_sync(0xffffffffu, sv[s], off);
            int oi = __shfl_xor_sync(0xffffffffu, ci[s], off);
            if (ov > bv[s]) {
                sv[s] = fmaxf(bv[s], os);
                bv[s] = ov;
                ci[s] = oi;
            } else {
                sv[s] = fmaxf(sv[s], ov);
            }
        }
    }

    // ---- cross-warp (nband) merge via smem scratch (B0 free now) ----
    float* mvS = (float*)(smem + SM_B0);
    float* msS = mvS + 256;
    int* miS = (int*)(msS + 256);
    __syncthreads();
    if ((lane & 3) == 0) {
#pragma unroll
        for (int s = 0; s < 4; s++) {
            int gr = wm + (s >> 1) * 16 + (s & 1) * 8 + (lane >> 2);  // 0..127
            int idx = nband * 128 + gr;
            mvS[idx] = bv[s];
            msS[idx] = sv[s];
            miS[idx] = ci[s];
        }
    }
    __syncthreads();
    if (tid < MTILE) {
        int gr = tid;
        float b0v = mvS[gr], s0v = msS[gr];
        int b0i = miS[gr];
        float b1v = mvS[128 + gr], s1v = msS[128 + gr];
        int b1i = miS[128 + gr];
        float b, s2;
        int biF;
        if (b1v > b0v) {
            b = b1v; biF = b1i; s2 = fmaxf(s1v, b0v);
        } else {
            b = b0v; biF = b0i; s2 = fmaxf(s0v, b1v);
        }
        int row = m0 + gr;
        g_besti[row] = biF;
        float thr = sqrtf(zln2[gr] * __uint_as_float(g_maxcl2)) + SCORESLACK;
        if (b - s2 <= thr) {
            int slot = atomicAdd(&g_nflag, 1);
            g_flags[slot] = row;
        }
    }
}

// ---------------------------------------------------------------------------
// fallback: exact fp32 re-scan for ambiguous rows (vectorized)
// ---------------------------------------------------------------------------
__global__ __launch_bounds__(256) void fallback_kernel(const float* __restrict__ z,
                                                       const float* __restrict__ cb) {
    __shared__ float4 zr4[D_DIM / 4];
    __shared__ float rv[256];
    __shared__ int ri[256];
    const int tid = threadIdx.x;
    const int nf = g_nflag;
    for (int f = blockIdx.x; f < nf; f += gridDim.x) {
        int row = g_flags[f];
        if (tid < D_DIM / 4)
            zr4[tid] = *(const float4*)(z + (size_t)row * D_DIM + tid * 4);
        __syncthreads();
        float bvv = CUDART_INF_F;
        int bii = 0;
#pragma unroll 2
        for (int kk = 0; kk < K_CODES / 256; kk++) {
            int k = tid + kk * 256;
            const float4* c4 = (const float4*)(cb + (size_t)k * D_DIM);
            float d0 = 0.f, d1 = 0.f, d2 = 0.f, d3 = 0.f;
#pragma unroll
            for (int q = 0; q < 16; q += 4) {
                float4 a0 = c4[q], a1 = c4[q + 1], a2 = c4[q + 2], a3 = c4[q + 3];
                float4 z0 = zr4[q], z1 = zr4[q + 1], z2 = zr4[q + 2], z3 = zr4[q + 3];
                d0 = fmaf(a0.x, z0.x, fmaf(a0.y, z0.y, fmaf(a0.z, z0.z, fmaf(a0.w, z0.w, d0))));
                d1 = fmaf(a1.x, z1.x, fmaf(a1.y, z1.y, fmaf(a1.z, z1.z, fmaf(a1.w, z1.w, d1))));
                d2 = fmaf(a2.x, z2.x, fmaf(a2.y, z2.y, fmaf(a2.z, z2.z, fmaf(a2.w, z2.w, d2))));
                d3 = fmaf(a3.x, z3.x, fmaf(a3.y, z3.y, fmaf(a3.z, z3.z, fmaf(a3.w, z3.w, d3))));
            }
            float dot = (d0 + d1) + (d2 + d3);
            float d = fmaf(-2.f, dot, g_cnorm[k]);
            if (d < bvv) { bvv = d; bii = k; }
        }
        rv[tid] = bvv;
        ri[tid] = bii;
        __syncthreads();
        for (int s = 128; s > 0; s >>= 1) {
            if (tid < s) {
                float ov = rv[tid + s];
                int oi = ri[tid + s];
                if (ov < rv[tid] || (ov == rv[tid] && oi < ri[tid])) {
                    rv[tid] = ov;
                    ri[tid] = oi;
                }
            }
            __syncthreads();
        }
        if (tid == 0) g_besti[row] = ri[0];
        __syncthreads();
    }
}

// ---------------------------------------------------------------------------
// output: gather codes, indices, commit partials
// ---------------------------------------------------------------------------
__global__ __launch_bounds__(256) void output_kernel(const float* __restrict__ z,
                                                     const float* __restrict__ cb,
                                                     float* __restrict__ out) {
    __shared__ float red[256];
    const int tid = threadIdx.x;
    const int m0 = blockIdx.x * 64;
    float lsum = 0.f;
#pragma unroll
    for (int it = 0; it < 16; it++) {
        int e = tid + it * 256;
        int row = e >> 6;
        int d = e & 63;
        int ci = g_besti[m0 + row];
        float cv = __ldg(cb + (size_t)ci * D_DIM + d);
        float zv = z[(size_t)(m0 + row) * D_DIM + d];
        float diff = cv - zv;
        lsum += diff * diff;
        out[(size_t)(m0 + row) * D_DIM + d] = cv;
    }
    if (tid < 64) out[CODES_ELEMS + m0 + tid] = (float)g_besti[m0 + tid];
    red[tid] = lsum;
    __syncthreads();
#pragma unroll
    for (int s = 128; s > 0; s >>= 1) {
        if (tid < s) red[tid] += red[tid + s];
        __syncthreads();
    }
    if (tid == 0) g_partials[blockIdx.x] = red[0];
}

// ---------------------------------------------------------------------------
__global__ void final_kernel(float* __restrict__ out) {
    __shared__ double dred[256];
    int tid = threadIdx.x;
    double s = 0.0;
    for (int i = tid; i < OUTBLOCKS; i += 256) s += (double)g_partials[i];
    dred[tid] = s;
    __syncthreads();
#pragma unroll
    for (int st = 128; st > 0; st >>= 1) {
        if (tid < st) dred[tid] += dred[tid + st];
        __syncthreads();
    }
    if (tid == 0)
        out[CODES_ELEMS + NVEC] = (float)(dred[0] / (double)CODES_ELEMS);
}

// noop at launch index 2 keeps vq_mma at the profiled slot (L mod 7 == 3).
__global__ void noop_kernel() {}

// ---------------------------------------------------------------------------
extern "C" void kernel_launch(void* const* d_in, const int* in_sizes, int n_in,
                              void* d_out, int out_size) {
    const float* z = (const float*)d_in[0];
    const float* cb = (const float*)d_in[1];
    if (n_in >= 2 && in_sizes[0] < in_sizes[1]) {
        const float* t = z; z = cb; cb = t;
    }
    float* out = (float*)d_out;

    cudaFuncSetAttribute(vq_mma_kernel,
                         cudaFuncAttributeMaxDynamicSharedMemorySize, SMEM_K2);

    reset_kernel<<<1, 1>>>();                              // 0
    prep_kernel<<<(K_CODES + 255) / 256, 256>>>(cb);       // 1
    noop_kernel<<<1, 32>>>();                              // 2
    vq_mma_kernel<<<NCTAS, 256, SMEM_K2>>>(z);             // 3  <- profiled slot
    fallback_kernel<<<256, 256>>>(z, cb);                  // 4
    output_kernel<<<OUTBLOCKS, 256>>>(z, cb, out);         // 5
    final_kernel<<<1, 256>>>(out);                         // 6
}